// round 6
// baseline (speedup 1.0000x reference)
#include <cuda_runtime.h>
#include <cuda_fp16.h>
#include <math.h>
#include <stdint.h>

#define BATCH 512
#define TSEQ  256
#define DIN   128
#define HID   256
#define G4    1024
#define FDIM  64
#define EDIM  320
#define DM    384
#define NMERG 394
#define NL1   512
#define NACT  8

#define NBLK   128   // persistent grid: 8 batch-tiles x 16 col-tiles
#define NGRP   16    // blocks per batch-group barrier

// ---------------- scratch (static device memory; no allocations) ----------------
__device__ __half d_xw[134217728];     // [T, B, 4H] fp16 pre-activations (permuted gates)
__device__ float d_hs[33554432];       // [B, T, H] hidden states
__device__ float d_hbuf[2 * BATCH * HID]; // double-buffered compact h
__device__ int   d_bar[8 * TSEQ];      // per (batch-group, step) barrier counters
__device__ float d_Wip[G4 * DIN];      // permuted W_ih
__device__ float d_Wp[G4 * HID];       // permuted W_hh
__device__ float d_bp[G4];             // permuted bias
__device__ float d_sf[BATCH * EDIM];   // state_full
__device__ float d_q[BATCH * EDIM];
__device__ float d_qk[BATCH * HID];
__device__ float d_Mkp[EDIM * HID];    // Wk @ proj_W
__device__ float d_MA1[EDIM * HID];    // Wv @ proj_W
__device__ float d_Amat[EDIM * HID];   // Wo @ Wv @ proj_W
__device__ float d_vconst[EDIM];
__device__ float d_aconst[EDIM];
__device__ float d_hbar[BATCH * HID];
__device__ float d_ao[BATCH * EDIM];
__device__ float d_ms[BATCH * DM];
__device__ float d_qfeat[BATCH * 10];
__device__ float d_merged[BATCH * NMERG];
__device__ float d_x1[BATCH * NL1];

// ---------------- tf32 helpers ----------------
__device__ __forceinline__ uint32_t f2tf32(float f) {
    uint32_t r; asm("cvt.rna.tf32.f32 %0, %1;" : "=r"(r) : "f"(f)); return r;
}
__device__ __forceinline__ void mma_tf32(float* c, uint32_t a0, uint32_t a1,
                                         uint32_t a2, uint32_t a3,
                                         uint32_t b0, uint32_t b1) {
    asm volatile("mma.sync.aligned.m16n8k8.row.col.f32.tf32.tf32.f32 "
        "{%0,%1,%2,%3}, {%4,%5,%6,%7}, {%8,%9}, {%0,%1,%2,%3};"
        : "+f"(c[0]), "+f"(c[1]), "+f"(c[2]), "+f"(c[3])
        : "r"(a0), "r"(a1), "r"(a2), "r"(a3), "r"(b0), "r"(b1));
}

// ---------------- weight permutation: column 4u+g = gate g of unit u ----------------
__global__ void permute_kernel(const float* __restrict__ W_ih, const float* __restrict__ W_hh,
                               const float* __restrict__ b_ih, const float* __restrict__ b_hh,
                               float* __restrict__ Wip, float* __restrict__ Wp, float* __restrict__ bp) {
    int n = blockIdx.x;            // 0..1023, permuted row
    int u = n >> 2, g = n & 3;
    int o = g * HID + u;           // original row
    for (int k = threadIdx.x; k < DIN; k += blockDim.x) Wip[n * DIN + k] = W_ih[o * DIN + k];
    for (int k = threadIdx.x; k < HID; k += blockDim.x) Wp[n * HID + k] = W_hh[o * HID + k];
    if (threadIdx.x == 0) bp[n] = b_ih[o] + b_hh[o];
}

// ---------------- big input GEMM (tf32 mma): xw[t,b,:] = X[b,t,:] @ Wip^T + bp -------
__global__ __launch_bounds__(256) void xw_gemm_tf32(
    const float* __restrict__ X, const float* __restrict__ Wip,
    const float* __restrict__ bp, __half* __restrict__ xw) {
    __shared__ float sA[128][40];   // [m][k-chunk], permuted k pairs
    __shared__ float sB[128][40];   // [n][k-chunk], permuted k pairs
    int m0 = blockIdx.y * 128;
    int n0 = blockIdx.x * 128;
    int tid = threadIdx.x;
    int wid = tid >> 5, lane = tid & 31;
    int g = lane >> 2, t4 = lane & 3;
    int warp_m = (wid & 1) * 64;
    int warp_n = (wid >> 1) * 32;

    float c[4][4][4];
    #pragma unroll
    for (int i = 0; i < 4; i++)
        #pragma unroll
        for (int j = 0; j < 4; j++)
            #pragma unroll
            for (int e = 0; e < 4; e++) c[i][j][e] = 0.f;

    for (int k0 = 0; k0 < DIN; k0 += 32) {
        #pragma unroll
        for (int it = 0; it < 2; it++) {
            int gi = it * 256 + tid;     // 0..511
            int row = gi >> 2;           // 0..127
            int s = gi & 3;              // k-group of 8
            {
                const float* src = X + (size_t)(m0 + row) * DIN + k0 + s * 8;
                float4 a = __ldg((const float4*)src);
                float4 b = __ldg((const float4*)(src + 4));
                float4 o0, o1;
                o0.x = __uint_as_float(f2tf32(a.x)); o0.y = __uint_as_float(f2tf32(b.x));
                o0.z = __uint_as_float(f2tf32(a.y)); o0.w = __uint_as_float(f2tf32(b.y));
                o1.x = __uint_as_float(f2tf32(a.z)); o1.y = __uint_as_float(f2tf32(b.z));
                o1.z = __uint_as_float(f2tf32(a.w)); o1.w = __uint_as_float(f2tf32(b.w));
                float* dst = &sA[row][s * 8];
                *(float4*)dst = o0; *(float4*)(dst + 4) = o1;
            }
            {
                const float* src = Wip + (size_t)(n0 + row) * DIN + k0 + s * 8;
                float4 a = __ldg((const float4*)src);
                float4 b = __ldg((const float4*)(src + 4));
                float4 o0, o1;
                o0.x = __uint_as_float(f2tf32(a.x)); o0.y = __uint_as_float(f2tf32(b.x));
                o0.z = __uint_as_float(f2tf32(a.y)); o0.w = __uint_as_float(f2tf32(b.y));
                o1.x = __uint_as_float(f2tf32(a.z)); o1.y = __uint_as_float(f2tf32(b.z));
                o1.z = __uint_as_float(f2tf32(a.w)); o1.w = __uint_as_float(f2tf32(b.w));
                float* dst = &sB[row][s * 8];
                *(float4*)dst = o0; *(float4*)(dst + 4) = o1;
            }
        }
        __syncthreads();
        #pragma unroll
        for (int kk = 0; kk < 4; kk++) {
            uint32_t br[4][2];
            #pragma unroll
            for (int j = 0; j < 4; j++) {
                float2 bv = *(const float2*)&sB[warp_n + 8 * j + g][kk * 8 + 2 * t4];
                br[j][0] = __float_as_uint(bv.x);
                br[j][1] = __float_as_uint(bv.y);
            }
            #pragma unroll
            for (int i = 0; i < 4; i++) {
                int r0 = warp_m + 16 * i + g;
                float2 lo = *(const float2*)&sA[r0][kk * 8 + 2 * t4];
                float2 hi = *(const float2*)&sA[r0 + 8][kk * 8 + 2 * t4];
                uint32_t a0 = __float_as_uint(lo.x);
                uint32_t a2 = __float_as_uint(lo.y);
                uint32_t a1 = __float_as_uint(hi.x);
                uint32_t a3 = __float_as_uint(hi.y);
                #pragma unroll
                for (int j = 0; j < 4; j++)
                    mma_tf32(c[i][j], a0, a1, a2, a3, br[j][0], br[j][1]);
            }
        }
        __syncthreads();
    }

    // epilogue: bias + fp16 half2 stores
    float2 bb[4];
    #pragma unroll
    for (int j = 0; j < 4; j++) {
        int col = n0 + warp_n + 8 * j + 2 * t4;
        bb[j].x = __ldg(bp + col); bb[j].y = __ldg(bp + col + 1);
    }
    #pragma unroll
    for (int i = 0; i < 4; i++) {
        int rlo = m0 + warp_m + 16 * i + g;
        int rhi = rlo + 8;
        __half* dlo = xw + ((size_t)(rlo & 255) * BATCH + (rlo >> 8)) * G4;
        __half* dhi = xw + ((size_t)(rhi & 255) * BATCH + (rhi >> 8)) * G4;
        #pragma unroll
        for (int j = 0; j < 4; j++) {
            int col = n0 + warp_n + 8 * j + 2 * t4;
            __half2 vlo = __floats2half2_rn(c[i][j][0] + bb[j].x, c[i][j][1] + bb[j].y);
            __half2 vhi = __floats2half2_rn(c[i][j][2] + bb[j].x, c[i][j][3] + bb[j].y);
            *(__half2*)(dlo + col) = vlo;
            *(__half2*)(dhi + col) = vhi;
        }
    }
}

// ---------------- persistent LSTM recurrence: tf32 tensor-core mma -------------------
__global__ __launch_bounds__(256, 1) void lstm_persist(
    const __half* __restrict__ xw, const float* __restrict__ Wp,
    float* __restrict__ hs, float* __restrict__ hbuf, int* __restrict__ bar)
{
    __shared__ float sA[64][264];
    int bx = blockIdx.x & 15;       // col tile
    int by = blockIdx.x >> 4;       // batch tile (group id)
    int n0 = bx * 64, m0 = by * 64;
    int tid = threadIdx.x;
    int wid = tid >> 5, lane = tid & 31;
    int g = lane >> 2, t4 = lane & 3;
    int warp_m = (wid & 1) * 32;
    int warp_n = (wid >> 1) * 16;
    int odd = lane & 1;

    // ---- preload B fragments (Wp^T, col-major k8 x n8) into registers, tf32 ----
    uint32_t breg[2][32][2];
    #pragma unroll
    for (int j = 0; j < 2; j++) {
        int col = n0 + warp_n + 8 * j + g;
        const float* wrow = Wp + (size_t)col * HID;
        #pragma unroll
        for (int kk = 0; kk < 32; kk++) {
            breg[j][kk][0] = f2tf32(__ldg(wrow + kk * 8 + t4));
            breg[j][kk][1] = f2tf32(__ldg(wrow + kk * 8 + t4 + 4));
        }
    }
    float creg[4] = {0.f, 0.f, 0.f, 0.f};
    volatile int* vbar = bar;

    // precompute epilogue row/unit coords
    int erow[2], eu;
    erow[0] = m0 + warp_m + g + (odd ? 8 : 0);
    erow[1] = erow[0] + 16;
    eu = ((n0 + warp_n) >> 2) + ((lane >> 1) & 1);   // + 2*j handled in loop

    for (int t = 0; t < TSEQ; t++) {
        float c[2][2][4];
        #pragma unroll
        for (int i = 0; i < 2; i++)
            #pragma unroll
            for (int j = 0; j < 2; j++)
                #pragma unroll
                for (int e = 0; e < 4; e++) c[i][j][e] = 0.f;

        if (t > 0) {
            const float* hp = hbuf + (size_t)(t & 1) * (BATCH * HID);
            #pragma unroll
            for (int itr = 0; itr < 8; itr++) {
                int gi = itr * 256 + tid;      // 0..2047
                int row = gi >> 5;             // 0..63
                int s = gi & 31;               // k-group of 8
                const float* src = hp + (size_t)(m0 + row) * HID + s * 8;
                float4 a = __ldcg((const float4*)src);
                float4 b = __ldcg((const float4*)(src + 4));
                float4 o0, o1;
                o0.x = __uint_as_float(f2tf32(a.x)); o0.y = __uint_as_float(f2tf32(b.x));
                o0.z = __uint_as_float(f2tf32(a.y)); o0.w = __uint_as_float(f2tf32(b.y));
                o1.x = __uint_as_float(f2tf32(a.z)); o1.y = __uint_as_float(f2tf32(b.z));
                o1.z = __uint_as_float(f2tf32(a.w)); o1.w = __uint_as_float(f2tf32(b.w));
                float* dst = &sA[row][s * 8];
                *(float4*)dst = o0;
                *(float4*)(dst + 4) = o1;
            }
            __syncthreads();
            #pragma unroll
            for (int kk = 0; kk < 32; kk++) {
                #pragma unroll
                for (int i = 0; i < 2; i++) {
                    int r0 = warp_m + 16 * i + g;
                    float2 lo = *(const float2*)&sA[r0][kk * 8 + 2 * t4];
                    float2 hi = *(const float2*)&sA[r0 + 8][kk * 8 + 2 * t4];
                    uint32_t a0 = __float_as_uint(lo.x);
                    uint32_t a2 = __float_as_uint(lo.y);
                    uint32_t a1 = __float_as_uint(hi.x);
                    uint32_t a3 = __float_as_uint(hi.y);
                    mma_tf32(c[i][0], a0, a1, a2, a3, breg[0][kk][0], breg[0][kk][1]);
                    mma_tf32(c[i][1], a0, a1, a2, a3, breg[1][kk][0], breg[1][kk][1]);
                }
            }
            __syncthreads();
        }

        // ---- epilogue: gate exchange via shfl, cell update ----
        const __half* xwt = xw + (size_t)t * BATCH * G4;
        float* hn = hbuf + (size_t)((t + 1) & 1) * (BATCH * HID);
        float hvreg[2][2];
        #pragma unroll
        for (int i = 0; i < 2; i++) {
            #pragma unroll
            for (int j = 0; j < 2; j++) {
                float u0 = odd ? c[i][j][0] : c[i][j][2];
                float u1 = odd ? c[i][j][1] : c[i][j][3];
                float rx0 = __shfl_xor_sync(0xffffffffu, u0, 1);
                float rx1 = __shfl_xor_sync(0xffffffffu, u1, 1);
                float gi, gf, gg, go;
                if (!odd) { gi = c[i][j][0]; gf = c[i][j][1]; gg = rx0; go = rx1; }
                else      { gi = rx0; gf = rx1; gg = c[i][j][2]; go = c[i][j][3]; }
                int brow = erow[i];
                int u = eu + 2 * j;
                uint2 raw = *(const uint2*)(xwt + (size_t)brow * G4 + 4 * u);
                float2 f01 = __half22float2(*reinterpret_cast<__half2*>(&raw.x));
                float2 f23 = __half22float2(*reinterpret_cast<__half2*>(&raw.y));
                gi += f01.x; gf += f01.y; gg += f23.x; go += f23.y;
                float i_ = 1.f / (1.f + expf(-gi));
                float f_ = 1.f / (1.f + expf(-gf));
                float g_ = tanhf(gg);
                float o_ = 1.f / (1.f + expf(-go));
                int ci = i * 2 + j;
                float cn = f_ * creg[ci] + i_ * g_;
                creg[ci] = cn;
                float hv = o_ * tanhf(cn);
                hvreg[i][j] = hv;
                hn[(size_t)brow * HID + u] = hv;
            }
        }

        // arrive early: hn visible, then archive hs while others arrive, then wait
        int bi = by * TSEQ + t;
        if (t < TSEQ - 1) {
            __threadfence();
            __syncthreads();
            if (tid == 0) atomicAdd(&bar[bi], 1);
        }
        #pragma unroll
        for (int i = 0; i < 2; i++)
            #pragma unroll
            for (int j = 0; j < 2; j++)
                hs[((size_t)erow[i] * TSEQ + t) * HID + eu + 2 * j] = hvreg[i][j];
        if (t < TSEQ - 1) {
            if (tid == 0) { while (vbar[bi] < NGRP) {} }
            __syncthreads();
        }
    }
}

// ---------------- medium GEMM: C = A @ op(W) + bias, opt relu ------------------------
// 64x64 tile, 256 threads, 4x4 microtile. Guards on all edges (K may be ragged).
template <bool TRANS, bool RELU>
__global__ __launch_bounds__(256) void gemm_med(
    const float* __restrict__ A, const float* __restrict__ W,
    const float* __restrict__ bias, float* __restrict__ C,
    int M, int N, int K, int lda, int ldw, int ldc) {
    __shared__ float sA[16][68];   // [k][m]
    __shared__ float sW[16][68];   // [k][n]
    int m0 = blockIdx.y * 64, n0 = blockIdx.x * 64;
    int tid = threadIdx.x;
    int tx = tid & 15, ty = tid >> 4;
    float acc[4][4] = {};
    for (int k0 = 0; k0 < K; k0 += 16) {
        #pragma unroll
        for (int i = 0; i < 4; i++) {
            int idx = tid + i * 256;
            int r = idx >> 4, k = idx & 15;
            int mm = m0 + r, kk = k0 + k;
            sA[k][r] = (mm < M && kk < K) ? A[(size_t)mm * lda + kk] : 0.f;
            int nn = n0 + r;
            float v = 0.f;
            if (TRANS) { if (kk < K && nn < N) v = W[(size_t)kk * ldw + nn]; }
            else       { if (nn < N && kk < K) v = W[(size_t)nn * ldw + kk]; }
            sW[k][r] = v;
        }
        __syncthreads();
        #pragma unroll
        for (int k = 0; k < 16; k++) {
            float4 a = *(const float4*)&sA[k][ty * 4];
            float4 b = *(const float4*)&sW[k][tx * 4];
            acc[0][0] += a.x * b.x; acc[0][1] += a.x * b.y; acc[0][2] += a.x * b.z; acc[0][3] += a.x * b.w;
            acc[1][0] += a.y * b.x; acc[1][1] += a.y * b.y; acc[1][2] += a.y * b.z; acc[1][3] += a.y * b.w;
            acc[2][0] += a.z * b.x; acc[2][1] += a.z * b.y; acc[2][2] += a.z * b.z; acc[2][3] += a.z * b.w;
            acc[3][0] += a.w * b.x; acc[3][1] += a.w * b.y; acc[3][2] += a.w * b.z; acc[3][3] += a.w * b.w;
        }
        __syncthreads();
    }
    #pragma unroll
    for (int r = 0; r < 4; r++) {
        int m = m0 + ty * 4 + r;
        if (m >= M) continue;
        #pragma unroll
        for (int cc = 0; cc < 4; cc++) {
            int n = n0 + tx * 4 + cc;
            if (n >= N) continue;
            float v = acc[r][cc];
            if (bias) v += bias[n];
            if (RELU) v = fmaxf(v, 0.f);
            C[(size_t)m * ldc + n] = v;
        }
    }
}

// ---------------- tiny matvec ----------------
__global__ void matvec(const float* __restrict__ W, const float* __restrict__ x,
                       const float* __restrict__ bias, float* __restrict__ y,
                       int N, int K, int ldw) {
    int i = blockIdx.x * blockDim.x + threadIdx.x;
    if (i >= N) return;
    float a = bias ? bias[i] : 0.f;
    for (int k = 0; k < K; k++) a += W[(size_t)i * ldw + k] * x[k];
    y[i] = a;
}

// ---------------- fused attention: scores, softmax, weighted hidden sum --------------
__global__ void attn_kernel(const float* __restrict__ hs, const float* __restrict__ qk,
                            float* __restrict__ hbar) {
    int b = blockIdx.x;
    __shared__ float sc[TSEQ];
    __shared__ float red[256];
    int tid = threadIdx.x;
    int lane = tid & 31, w = tid >> 5;
    for (int t = w; t < TSEQ; t += 8) {
        const float* hrow = hs + ((size_t)b * TSEQ + t) * HID;
        float p = 0.f;
        #pragma unroll
        for (int j = 0; j < 8; j++) {
            int h0 = lane + 32 * j;
            p += hrow[h0] * qk[b * HID + h0];
        }
        #pragma unroll
        for (int o = 16; o > 0; o >>= 1) p += __shfl_down_sync(0xffffffffu, p, o);
        if (lane == 0) sc[t] = p;
    }
    __syncthreads();
    float scale = 1.0f / sqrtf((float)EDIM);
    float v = sc[tid] * scale;
    red[tid] = v; __syncthreads();
    for (int s = 128; s > 0; s >>= 1) { if (tid < s) red[tid] = fmaxf(red[tid], red[tid + s]); __syncthreads(); }
    float mx = red[0]; __syncthreads();
    float ev = expf(v - mx);
    red[tid] = ev; __syncthreads();
    for (int s = 128; s > 0; s >>= 1) { if (tid < s) red[tid] += red[tid + s]; __syncthreads(); }
    float sum = red[0]; __syncthreads();
    sc[tid] = ev / sum;
    __syncthreads();
    const float* hb = hs + (size_t)b * TSEQ * HID;
    float acc = 0.f;
    for (int t = 0; t < TSEQ; t++) acc += sc[t] * hb[(size_t)t * HID + tid];
    hbar[b * HID + tid] = acc;
}

// ---------------- concat helpers ----------------
__global__ void sf_build(const float* __restrict__ hs, const float* __restrict__ s,
                         float* __restrict__ sf) {
    int idx = blockIdx.x * blockDim.x + threadIdx.x;
    if (idx >= BATCH * EDIM) return;
    int b = idx / EDIM, j = idx % EDIM;
    sf[idx] = (j < HID) ? hs[((size_t)b * TSEQ + (TSEQ - 1)) * HID + j] : s[b * FDIM + (j - HID)];
}
__global__ void ms_build(const float* __restrict__ ao, const float* __restrict__ s,
                         float* __restrict__ ms) {
    int idx = blockIdx.x * blockDim.x + threadIdx.x;
    if (idx >= BATCH * DM) return;
    int b = idx / DM, j = idx % DM;
    ms[idx] = (j < EDIM) ? ao[b * EDIM + j] : s[b * FDIM + (j - EDIM)];
}
__global__ void merged_build(const float* __restrict__ ms, const float* __restrict__ qf,
                             float* __restrict__ mg) {
    int idx = blockIdx.x * blockDim.x + threadIdx.x;
    if (idx >= BATCH * NMERG) return;
    int b = idx / NMERG, j = idx % NMERG;
    mg[idx] = (j < DM) ? ms[b * DM + j] : qf[b * 10 + (j - DM)];
}

// ---------------- 10-qubit VQC, one block per batch element --------------------------
struct c2f { float x, y; };
__device__ __forceinline__ c2f cmul(c2f a, c2f b) { return { a.x * b.x - a.y * b.y, a.x * b.y + a.y * b.x }; }
__device__ __forceinline__ c2f cadd(c2f a, c2f b) { return { a.x + b.x, a.y + b.y }; }
__device__ __forceinline__ void matmul2(c2f C[2][2], const c2f A[2][2], const c2f B[2][2]) {
    #pragma unroll
    for (int i = 0; i < 2; i++)
        #pragma unroll
        for (int j = 0; j < 2; j++)
            C[i][j] = cadd(cmul(A[i][0], B[0][j]), cmul(A[i][1], B[1][j]));
}

__global__ void vqc_kernel(const float* __restrict__ ms, const float* __restrict__ qw,
                           float* __restrict__ qfeat) {
    int b = blockIdx.x;
    __shared__ c2f psi[1024];
    __shared__ float red[512];
    __shared__ float sang[40];
    int tid = threadIdx.x;
    const float PI_F = 3.14159265358979323846f;
    psi[tid] = { 0.03125f, 0.f };
    psi[tid + 512] = { 0.03125f, 0.f };
    if (tid < 40) sang[tid] = tanhf(ms[b * DM + tid]) * PI_F;
    __syncthreads();

    for (int layer = 0; layer < 4; layer++) {
        for (int q = 0; q < 10; q++) {
            int idx = layer * 10 + q;
            float a = sang[idx];
            float w0 = qw[idx * 3 + 0], w1 = qw[idx * 3 + 1], w2 = qw[idx * 3 + 2];
            float ch, sh; sincosf(0.5f * a, &sh, &ch);
            c2f Rx[2][2] = { { {ch, 0.f}, {0.f, -sh} }, { {0.f, -sh}, {ch, 0.f} } };
            c2f Rya[2][2] = { { {ch, 0.f}, {-sh, 0.f} }, { {sh, 0.f}, {ch, 0.f} } };
            c2f T1[2][2]; matmul2(T1, Rya, Rx);
            float c0, s0; sincosf(0.5f * w0, &s0, &c0);
            c2f Rz0[2][2] = { { {c0, -s0}, {0.f, 0.f} }, { {0.f, 0.f}, {c0, s0} } };
            c2f T2[2][2]; matmul2(T2, Rz0, T1);
            float c1, s1; sincosf(0.5f * w1, &s1, &c1);
            c2f Ry1[2][2] = { { {c1, 0.f}, {-s1, 0.f} }, { {s1, 0.f}, {c1, 0.f} } };
            c2f T3[2][2]; matmul2(T3, Ry1, T2);
            float c2r, s2r; sincosf(0.5f * w2, &s2r, &c2r);
            c2f Rz2[2][2] = { { {c2r, -s2r}, {0.f, 0.f} }, { {0.f, 0.f}, {c2r, s2r} } };
            c2f U[2][2]; matmul2(U, Rz2, T3);

            int bq = 9 - q;
            int low = tid & ((1 << bq) - 1);
            int i0 = ((tid >> bq) << (bq + 1)) | low;
            int i1 = i0 | (1 << bq);
            __syncthreads();
            c2f a0 = psi[i0], a1 = psi[i1];
            psi[i0] = cadd(cmul(U[0][0], a0), cmul(U[0][1], a1));
            psi[i1] = cadd(cmul(U[1][0], a0), cmul(U[1][1], a1));
        }
        for (int qq = 0; qq < 10; qq++) {
            int ctrl = (qq < 9) ? qq : 9;
            int tgt  = (qq < 9) ? qq + 1 : 0;
            int bc = 9 - ctrl, bt = 9 - tgt;
            __syncthreads();
            if (tid < 256) {
                int lo = min(bc, bt), hi = max(bc, bt);
                int i = tid;
                i = ((i >> lo) << (lo + 1)) | (i & ((1 << lo) - 1));
                i = ((i >> hi) << (hi + 1)) | (i & ((1 << hi) - 1));
                i |= (1 << bc);
                int j0 = i;
                int j1 = i | (1 << bt);
                c2f tmp = psi[j0]; psi[j0] = psi[j1]; psi[j1] = tmp;
            }
        }
    }
    __syncthreads();
    c2f p0 = psi[tid], p1 = psi[tid + 512];
    float n0 = p0.x * p0.x + p0.y * p0.y;
    float n1 = p1.x * p1.x + p1.y * p1.y;
    for (int k = 0; k < 10; k++) {
        int bp = 9 - k;
        float s0v = ((tid >> bp) & 1) ? -n0 : n0;
        float s1v = (((tid + 512) >> bp) & 1) ? -n1 : n1;
        red[tid] = s0v + s1v;
        __syncthreads();
        for (int s = 256; s > 0; s >>= 1) { if (tid < s) red[tid] += red[tid + s]; __syncthreads(); }
        if (tid == 0) qfeat[b * 10 + k] = red[0];
        __syncthreads();
    }
}

// ---------------- host launch ----------------
#define GETSYM(p, sym) do { void* _t = nullptr; cudaGetSymbolAddress(&_t, sym); (p) = (float*)_t; } while (0)

extern "C" void kernel_launch(void* const* d_in, const int* in_sizes, int n_in,
                              void* d_out, int out_size) {
    const float* s          = (const float*)d_in[0];
    const float* lstm_s     = (const float*)d_in[1];
    const float* W_ih       = (const float*)d_in[2];
    const float* W_hh       = (const float*)d_in[3];
    const float* b_ih       = (const float*)d_in[4];
    const float* b_hh       = (const float*)d_in[5];
    const float* proj_W     = (const float*)d_in[6];
    const float* proj_b     = (const float*)d_in[7];
    const float* in_proj_W  = (const float*)d_in[8];
    const float* in_proj_b  = (const float*)d_in[9];
    const float* out_proj_W = (const float*)d_in[10];
    const float* out_proj_b = (const float*)d_in[11];
    const float* qweights   = (const float*)d_in[12];
    const float* W1         = (const float*)d_in[13];
    const float* b1         = (const float*)d_in[14];
    const float* W2         = (const float*)d_in[15];
    const float* b2         = (const float*)d_in[16];
    float* out = (float*)d_out;

    float *hs, *hbuf, *Wip, *Wp, *bp, *sf, *qv, *qk, *Mkp, *MA1, *Amat;
    float *vconst, *aconst, *hbar, *ao, *msb, *qfeat, *merged, *x1;
    __half* xw;
    int* bar;
    { void* _t = nullptr; cudaGetSymbolAddress(&_t, d_xw); xw = (__half*)_t; }
    GETSYM(hs, d_hs);   GETSYM(hbuf, d_hbuf);
    GETSYM(Wip, d_Wip); GETSYM(Wp, d_Wp);   GETSYM(bp, d_bp);   GETSYM(sf, d_sf);
    GETSYM(qv, d_q);    GETSYM(qk, d_qk);   GETSYM(Mkp, d_Mkp); GETSYM(MA1, d_MA1);
    GETSYM(Amat, d_Amat); GETSYM(vconst, d_vconst); GETSYM(aconst, d_aconst);
    GETSYM(hbar, d_hbar); GETSYM(ao, d_ao); GETSYM(msb, d_ms);  GETSYM(qfeat, d_qfeat);
    GETSYM(merged, d_merged); GETSYM(x1, d_x1);
    { void* _t = nullptr; cudaGetSymbolAddress(&_t, d_bar); bar = (int*)_t; }

    const float* Wq = in_proj_W;
    const float* Wk = in_proj_W + EDIM * EDIM;
    const float* Wv = in_proj_W + 2 * EDIM * EDIM;
    const float* bq = in_proj_b;
    const float* bv = in_proj_b + 2 * EDIM;

    cudaMemsetAsync(bar, 0, 8 * TSEQ * sizeof(int));

    // weight permutation (gate-interleaved)
    permute_kernel<<<G4, 128>>>(W_ih, W_hh, b_ih, b_hh, Wip, Wp, bp);

    // big input GEMM (tf32 tensor cores): xw[t,b,:] = X @ Wip^T + bp (fp16 out)
    xw_gemm_tf32<<<dim3(G4 / 128, (BATCH * TSEQ) / 128), 256>>>(lstm_s, Wip, bp, xw);

    // persistent LSTM recurrence (all 256 steps, one kernel, tf32 tensor cores)
    lstm_persist<<<NBLK, 256>>>(xw, Wp, hs, hbuf, bar);

    // state_full = [h_last, s]; q = sf @ Wq^T + bq
    sf_build<<<(BATCH * EDIM + 255) / 256, 256>>>(hs, s, sf);
    gemm_med<false, false><<<dim3(5, 8), 256>>>(sf, Wq, bq, qv, BATCH, EDIM, EDIM, EDIM, EDIM, EDIM);

    // precompose attention matrices
    gemm_med<true, false><<<dim3(4, 5), 256>>>(Wk, proj_W, nullptr, Mkp, EDIM, HID, EDIM, EDIM, HID, HID);
    gemm_med<true, false><<<dim3(4, 8), 256>>>(qv, Mkp, nullptr, qk, BATCH, HID, EDIM, EDIM, HID, HID);
    gemm_med<true, false><<<dim3(4, 5), 256>>>(Wv, proj_W, nullptr, MA1, EDIM, HID, EDIM, EDIM, HID, HID);
    gemm_med<true, false><<<dim3(4, 5), 256>>>(out_proj_W, MA1, nullptr, Amat, EDIM, HID, EDIM, EDIM, HID, HID);
    matvec<<<1, EDIM>>>(Wv, proj_b, bv, vconst, EDIM, EDIM, EDIM);
    matvec<<<1, EDIM>>>(out_proj_W, vconst, out_proj_b, aconst, EDIM, EDIM, EDIM);

    // fused attention over hs
    attn_kernel<<<BATCH, 256>>>(hs, qk, hbar);

    // attn_out = hbar @ Amat^T + aconst; merged_state = [attn_out, s]
    gemm_med<false, false><<<dim3(5, 8), 256>>>(hbar, Amat, aconst, ao, BATCH, EDIM, HID, HID, HID, EDIM);
    ms_build<<<(BATCH * DM + 255) / 256, 256>>>(ao, s, msb);

    // VQC
    vqc_kernel<<<BATCH, 512>>>(msb, qweights, qfeat);

    // MLP
    merged_build<<<(BATCH * NMERG + 255) / 256, 256>>>(msb, qfeat, merged);
    gemm_med<false, true><<<dim3(8, 8), 256>>>(merged, W1, b1, x1, BATCH, NL1, NMERG, NMERG, NMERG, NL1);
    gemm_med<false, false><<<dim3(1, 8), 256>>>(x1, W2, b2, out, BATCH, NACT, NL1, NL1, NL1, NACT);
}

// round 7
// speedup vs baseline: 1.2191x; 1.2191x over previous
#include <cuda_runtime.h>
#include <cuda_fp16.h>
#include <math.h>
#include <stdint.h>

#define BATCH 512
#define TSEQ  256
#define DIN   128
#define HID   256
#define G4    1024
#define FDIM  64
#define EDIM  320
#define DM    384
#define NMERG 394
#define NL1   512
#define NACT  8

#define NBLK   128   // persistent grid: 8 batch-tiles x 16 col-tiles
#define NGRP   16    // blocks per batch-group barrier

// ---------------- scratch (static device memory; no allocations) ----------------
__device__ __half d_xw[134217728];     // [T, B, 4H] fp16 pre-activations (permuted gates)
__device__ float d_hs[33554432];       // [B, T, H] hidden states
__device__ __half d_hbuf[2 * BATCH * HID]; // double-buffered compact h (fp16)
__device__ int   d_bar[8 * TSEQ];      // per (batch-group, step) barrier counters
__device__ float d_Wip[G4 * DIN];      // permuted W_ih
__device__ float d_Wp[G4 * HID];       // permuted W_hh
__device__ float d_bp[G4];             // permuted bias
__device__ float d_sf[BATCH * EDIM];   // state_full
__device__ float d_q[BATCH * EDIM];
__device__ float d_qk[BATCH * HID];
__device__ float d_Mkp[EDIM * HID];    // Wk @ proj_W
__device__ float d_MA1[EDIM * HID];    // Wv @ proj_W
__device__ float d_Amat[EDIM * HID];   // Wo @ Wv @ proj_W
__device__ float d_vconst[EDIM];
__device__ float d_aconst[EDIM];
__device__ float d_hbar[BATCH * HID];
__device__ float d_ao[BATCH * EDIM];
__device__ float d_ms[BATCH * DM];
__device__ float d_qfeat[BATCH * 10];
__device__ float d_merged[BATCH * NMERG];
__device__ float d_x1[BATCH * NL1];

// ---------------- fp16 mma helpers ----------------
__device__ __forceinline__ uint32_t pack_h2(float x, float y) {
    __half2 t = __floats2half2_rn(x, y);
    return *reinterpret_cast<uint32_t*>(&t);
}
__device__ __forceinline__ void mma_f16(float* c, uint32_t a0, uint32_t a1,
                                        uint32_t a2, uint32_t a3,
                                        uint32_t b0, uint32_t b1) {
    asm volatile("mma.sync.aligned.m16n8k16.row.col.f32.f16.f16.f32 "
        "{%0,%1,%2,%3}, {%4,%5,%6,%7}, {%8,%9}, {%0,%1,%2,%3};"
        : "+f"(c[0]), "+f"(c[1]), "+f"(c[2]), "+f"(c[3])
        : "r"(a0), "r"(a1), "r"(a2), "r"(a3), "r"(b0), "r"(b1));
}

// ---------------- weight permutation: column 4u+g = gate g of unit u ----------------
__global__ void permute_kernel(const float* __restrict__ W_ih, const float* __restrict__ W_hh,
                               const float* __restrict__ b_ih, const float* __restrict__ b_hh,
                               float* __restrict__ Wip, float* __restrict__ Wp, float* __restrict__ bp) {
    int n = blockIdx.x;            // 0..1023, permuted row
    int u = n >> 2, g = n & 3;
    int o = g * HID + u;           // original row
    for (int k = threadIdx.x; k < DIN; k += blockDim.x) Wip[n * DIN + k] = W_ih[o * DIN + k];
    for (int k = threadIdx.x; k < HID; k += blockDim.x) Wp[n * HID + k] = W_hh[o * HID + k];
    if (threadIdx.x == 0) bp[n] = b_ih[o] + b_hh[o];
}

// ---------------- big input GEMM (fp16 mma): xw[t,b,:] = X[b,t,:] @ Wip^T + bp -------
// 128x128 block tile, K=128 in k64 chunks. 8 warps, warp tile 64m x 32n, m16n8k16.
__global__ __launch_bounds__(256) void xw_gemm_f16(
    const float* __restrict__ X, const float* __restrict__ Wip,
    const float* __restrict__ bp, __half* __restrict__ xw) {
    __shared__ __half sA[128][72];   // [m][k-chunk], stride 72 halves (36 words)
    __shared__ __half sB[128][72];   // [n][k-chunk]
    int m0 = blockIdx.y * 128;
    int n0 = blockIdx.x * 128;
    int tid = threadIdx.x;
    int wid = tid >> 5, lane = tid & 31;
    int g = lane >> 2, t4 = lane & 3;
    int warp_m = (wid & 1) * 64;
    int warp_n = (wid >> 1) * 32;

    float c[4][4][4];
    #pragma unroll
    for (int i = 0; i < 4; i++)
        #pragma unroll
        for (int j = 0; j < 4; j++)
            #pragma unroll
            for (int e = 0; e < 4; e++) c[i][j][e] = 0.f;

    for (int k0 = 0; k0 < DIN; k0 += 64) {
        #pragma unroll
        for (int it = 0; it < 8; it++) {
            int gi = it * 256 + tid;     // 0..2047
            int row = gi >> 4;           // 0..127
            int c4 = gi & 15;            // chunk of 4 floats within k64
            {
                float4 v = __ldg((const float4*)(X + (size_t)(m0 + row) * DIN + k0 + c4 * 4));
                uint2 pk = { pack_h2(v.x, v.y), pack_h2(v.z, v.w) };
                *(uint2*)&sA[row][c4 * 4] = pk;
            }
            {
                float4 v = __ldg((const float4*)(Wip + (size_t)(n0 + row) * DIN + k0 + c4 * 4));
                uint2 pk = { pack_h2(v.x, v.y), pack_h2(v.z, v.w) };
                *(uint2*)&sB[row][c4 * 4] = pk;
            }
        }
        __syncthreads();
        #pragma unroll
        for (int kk = 0; kk < 4; kk++) {
            uint32_t br[4][2];
            #pragma unroll
            for (int j = 0; j < 4; j++) {
                const __half* bsrc = &sB[warp_n + 8 * j + g][kk * 16 + 2 * t4];
                br[j][0] = *(const uint32_t*)bsrc;
                br[j][1] = *(const uint32_t*)(bsrc + 8);
            }
            #pragma unroll
            for (int i = 0; i < 4; i++) {
                int r0 = warp_m + 16 * i + g;
                const __half* alo = &sA[r0][kk * 16 + 2 * t4];
                const __half* ahi = &sA[r0 + 8][kk * 16 + 2 * t4];
                uint32_t a0 = *(const uint32_t*)alo;
                uint32_t a2 = *(const uint32_t*)(alo + 8);
                uint32_t a1 = *(const uint32_t*)ahi;
                uint32_t a3 = *(const uint32_t*)(ahi + 8);
                #pragma unroll
                for (int j = 0; j < 4; j++)
                    mma_f16(c[i][j], a0, a1, a2, a3, br[j][0], br[j][1]);
            }
        }
        __syncthreads();
    }

    // epilogue: bias + fp16 half2 stores
    float2 bb[4];
    #pragma unroll
    for (int j = 0; j < 4; j++) {
        int col = n0 + warp_n + 8 * j + 2 * t4;
        bb[j].x = __ldg(bp + col); bb[j].y = __ldg(bp + col + 1);
    }
    #pragma unroll
    for (int i = 0; i < 4; i++) {
        int rlo = m0 + warp_m + 16 * i + g;
        int rhi = rlo + 8;
        __half* dlo = xw + ((size_t)(rlo & 255) * BATCH + (rlo >> 8)) * G4;
        __half* dhi = xw + ((size_t)(rhi & 255) * BATCH + (rhi >> 8)) * G4;
        #pragma unroll
        for (int j = 0; j < 4; j++) {
            int col = n0 + warp_n + 8 * j + 2 * t4;
            __half2 vlo = __floats2half2_rn(c[i][j][0] + bb[j].x, c[i][j][1] + bb[j].y);
            __half2 vhi = __floats2half2_rn(c[i][j][2] + bb[j].x, c[i][j][3] + bb[j].y);
            *(__half2*)(dlo + col) = vlo;
            *(__half2*)(dhi + col) = vhi;
        }
    }
}

// ---------------- persistent LSTM recurrence: fp16 tensor-core mma -------------------
// 128 blocks (by=batch-tile of 64, bx=gatecol-tile of 64), 256 threads = 8 warps.
// Warp tile m32 x n16 via mma.m16n8k16 f16. Wp fragments register-resident; h in fp16.
__global__ __launch_bounds__(256, 1) void lstm_persist(
    const __half* __restrict__ xw, const float* __restrict__ Wp,
    float* __restrict__ hs, __half* __restrict__ hbuf, int* __restrict__ bar)
{
    __shared__ __half sA[64][264];   // [m][k] halves, stride 264 (132 words)
    int bx = blockIdx.x & 15;       // col tile
    int by = blockIdx.x >> 4;       // batch tile (group id)
    int n0 = bx * 64, m0 = by * 64;
    int tid = threadIdx.x;
    int wid = tid >> 5, lane = tid & 31;
    int g = lane >> 2, t4 = lane & 3;
    int warp_m = (wid & 1) * 32;
    int warp_n = (wid >> 1) * 16;
    int odd = lane & 1;

    // ---- preload B fragments (Wp^T, col-major k16 x n8) into registers, fp16 ----
    uint32_t breg[2][16][2];
    #pragma unroll
    for (int j = 0; j < 2; j++) {
        int col = n0 + warp_n + 8 * j + g;
        const float* wrow = Wp + (size_t)col * HID;
        #pragma unroll
        for (int kk = 0; kk < 16; kk++) {
            breg[j][kk][0] = pack_h2(__ldg(wrow + kk * 16 + 2 * t4),
                                     __ldg(wrow + kk * 16 + 2 * t4 + 1));
            breg[j][kk][1] = pack_h2(__ldg(wrow + kk * 16 + 2 * t4 + 8),
                                     __ldg(wrow + kk * 16 + 2 * t4 + 9));
        }
    }
    float creg[4] = {0.f, 0.f, 0.f, 0.f};
    volatile int* vbar = bar;

    // epilogue row/unit coords
    int erow[2], eu;
    erow[0] = m0 + warp_m + g + (odd ? 8 : 0);
    erow[1] = erow[0] + 16;
    eu = ((n0 + warp_n) >> 2) + ((lane >> 1) & 1);

    for (int t = 0; t < TSEQ; t++) {
        float c[2][2][4];
        #pragma unroll
        for (int i = 0; i < 2; i++)
            #pragma unroll
            for (int j = 0; j < 2; j++)
                #pragma unroll
                for (int e = 0; e < 4; e++) c[i][j][e] = 0.f;

        if (t > 0) {
            const __half* hp = hbuf + (size_t)(t & 1) * (BATCH * HID);
            // fill: 64 rows x 256 halves = 32 KB; one uint4 (8 halves) per thread/iter
            #pragma unroll
            for (int itr = 0; itr < 8; itr++) {
                int gi = itr * 256 + tid;      // 0..2047
                int row = gi >> 5;             // 0..63
                int s = gi & 31;               // 16B chunk within row
                uint4 v = __ldcg((const uint4*)(hp + (size_t)(m0 + row) * HID + s * 8));
                *(uint4*)&sA[row][s * 8] = v;
            }
            __syncthreads();
            #pragma unroll
            for (int kk = 0; kk < 16; kk++) {
                #pragma unroll
                for (int i = 0; i < 2; i++) {
                    int r0 = warp_m + 16 * i + g;
                    const __half* alo = &sA[r0][kk * 16 + 2 * t4];
                    const __half* ahi = &sA[r0 + 8][kk * 16 + 2 * t4];
                    uint32_t a0 = *(const uint32_t*)alo;
                    uint32_t a2 = *(const uint32_t*)(alo + 8);
                    uint32_t a1 = *(const uint32_t*)ahi;
                    uint32_t a3 = *(const uint32_t*)(ahi + 8);
                    mma_f16(c[i][0], a0, a1, a2, a3, breg[0][kk][0], breg[0][kk][1]);
                    mma_f16(c[i][1], a0, a1, a2, a3, breg[1][kk][0], breg[1][kk][1]);
                }
            }
            __syncthreads();
        }

        // ---- epilogue: gate exchange via shfl, cell update ----
        const __half* xwt = xw + (size_t)t * BATCH * G4;
        __half* hn = hbuf + (size_t)((t + 1) & 1) * (BATCH * HID);
        float hvreg[2][2];
        #pragma unroll
        for (int i = 0; i < 2; i++) {
            #pragma unroll
            for (int j = 0; j < 2; j++) {
                float u0 = odd ? c[i][j][0] : c[i][j][2];
                float u1 = odd ? c[i][j][1] : c[i][j][3];
                float rx0 = __shfl_xor_sync(0xffffffffu, u0, 1);
                float rx1 = __shfl_xor_sync(0xffffffffu, u1, 1);
                float gi, gf, gg, go;
                if (!odd) { gi = c[i][j][0]; gf = c[i][j][1]; gg = rx0; go = rx1; }
                else      { gi = rx0; gf = rx1; gg = c[i][j][2]; go = c[i][j][3]; }
                int brow = erow[i];
                int u = eu + 2 * j;
                uint2 raw = *(const uint2*)(xwt + (size_t)brow * G4 + 4 * u);
                float2 f01 = __half22float2(*reinterpret_cast<__half2*>(&raw.x));
                float2 f23 = __half22float2(*reinterpret_cast<__half2*>(&raw.y));
                gi += f01.x; gf += f01.y; gg += f23.x; go += f23.y;
                float i_ = 1.f / (1.f + expf(-gi));
                float f_ = 1.f / (1.f + expf(-gf));
                float g_ = tanhf(gg);
                float o_ = 1.f / (1.f + expf(-go));
                int ci = i * 2 + j;
                float cn = f_ * creg[ci] + i_ * g_;
                creg[ci] = cn;
                float hv = o_ * tanhf(cn);
                hvreg[i][j] = hv;
                hn[(size_t)brow * HID + u] = __float2half_rn(hv);
            }
        }

        // arrive early: hn visible, archive hs while others arrive, then wait
        int bi = by * TSEQ + t;
        if (t < TSEQ - 1) {
            __threadfence();
            __syncthreads();
            if (tid == 0) atomicAdd(&bar[bi], 1);
        }
        #pragma unroll
        for (int i = 0; i < 2; i++)
            #pragma unroll
            for (int j = 0; j < 2; j++)
                hs[((size_t)erow[i] * TSEQ + t) * HID + eu + 2 * j] = hvreg[i][j];
        if (t < TSEQ - 1) {
            if (tid == 0) { while (vbar[bi] < NGRP) {} }
            __syncthreads();
        }
    }
}

// ---------------- medium GEMM: C = A @ op(W) + bias, opt relu ------------------------
template <bool TRANS, bool RELU>
__global__ __launch_bounds__(256) void gemm_med(
    const float* __restrict__ A, const float* __restrict__ W,
    const float* __restrict__ bias, float* __restrict__ C,
    int M, int N, int K, int lda, int ldw, int ldc) {
    __shared__ float sA[16][68];   // [k][m]
    __shared__ float sW[16][68];   // [k][n]
    int m0 = blockIdx.y * 64, n0 = blockIdx.x * 64;
    int tid = threadIdx.x;
    int tx = tid & 15, ty = tid >> 4;
    float acc[4][4] = {};
    for (int k0 = 0; k0 < K; k0 += 16) {
        #pragma unroll
        for (int i = 0; i < 4; i++) {
            int idx = tid + i * 256;
            int r = idx >> 4, k = idx & 15;
            int mm = m0 + r, kk = k0 + k;
            sA[k][r] = (mm < M && kk < K) ? A[(size_t)mm * lda + kk] : 0.f;
            int nn = n0 + r;
            float v = 0.f;
            if (TRANS) { if (kk < K && nn < N) v = W[(size_t)kk * ldw + nn]; }
            else       { if (nn < N && kk < K) v = W[(size_t)nn * ldw + kk]; }
            sW[k][r] = v;
        }
        __syncthreads();
        #pragma unroll
        for (int k = 0; k < 16; k++) {
            float4 a = *(const float4*)&sA[k][ty * 4];
            float4 b = *(const float4*)&sW[k][tx * 4];
            acc[0][0] += a.x * b.x; acc[0][1] += a.x * b.y; acc[0][2] += a.x * b.z; acc[0][3] += a.x * b.w;
            acc[1][0] += a.y * b.x; acc[1][1] += a.y * b.y; acc[1][2] += a.y * b.z; acc[1][3] += a.y * b.w;
            acc[2][0] += a.z * b.x; acc[2][1] += a.z * b.y; acc[2][2] += a.z * b.z; acc[2][3] += a.z * b.w;
            acc[3][0] += a.w * b.x; acc[3][1] += a.w * b.y; acc[3][2] += a.w * b.z; acc[3][3] += a.w * b.w;
        }
        __syncthreads();
    }
    #pragma unroll
    for (int r = 0; r < 4; r++) {
        int m = m0 + ty * 4 + r;
        if (m >= M) continue;
        #pragma unroll
        for (int cc = 0; cc < 4; cc++) {
            int n = n0 + tx * 4 + cc;
            if (n >= N) continue;
            float v = acc[r][cc];
            if (bias) v += bias[n];
            if (RELU) v = fmaxf(v, 0.f);
            C[(size_t)m * ldc + n] = v;
        }
    }
}

// ---------------- tiny matvec ----------------
__global__ void matvec(const float* __restrict__ W, const float* __restrict__ x,
                       const float* __restrict__ bias, float* __restrict__ y,
                       int N, int K, int ldw) {
    int i = blockIdx.x * blockDim.x + threadIdx.x;
    if (i >= N) return;
    float a = bias ? bias[i] : 0.f;
    for (int k = 0; k < K; k++) a += W[(size_t)i * ldw + k] * x[k];
    y[i] = a;
}

// ---------------- fused attention: scores, softmax, weighted hidden sum --------------
__global__ void attn_kernel(const float* __restrict__ hs, const float* __restrict__ qk,
                            float* __restrict__ hbar) {
    int b = blockIdx.x;
    __shared__ float sc[TSEQ];
    __shared__ float red[256];
    int tid = threadIdx.x;
    int lane = tid & 31, w = tid >> 5;
    for (int t = w; t < TSEQ; t += 8) {
        const float* hrow = hs + ((size_t)b * TSEQ + t) * HID;
        float p = 0.f;
        #pragma unroll
        for (int j = 0; j < 8; j++) {
            int h0 = lane + 32 * j;
            p += hrow[h0] * qk[b * HID + h0];
        }
        #pragma unroll
        for (int o = 16; o > 0; o >>= 1) p += __shfl_down_sync(0xffffffffu, p, o);
        if (lane == 0) sc[t] = p;
    }
    __syncthreads();
    float scale = 1.0f / sqrtf((float)EDIM);
    float v = sc[tid] * scale;
    red[tid] = v; __syncthreads();
    for (int s = 128; s > 0; s >>= 1) { if (tid < s) red[tid] = fmaxf(red[tid], red[tid + s]); __syncthreads(); }
    float mx = red[0]; __syncthreads();
    float ev = expf(v - mx);
    red[tid] = ev; __syncthreads();
    for (int s = 128; s > 0; s >>= 1) { if (tid < s) red[tid] += red[tid + s]; __syncthreads(); }
    float sum = red[0]; __syncthreads();
    sc[tid] = ev / sum;
    __syncthreads();
    const float* hb = hs + (size_t)b * TSEQ * HID;
    float acc = 0.f;
    for (int t = 0; t < TSEQ; t++) acc += sc[t] * hb[(size_t)t * HID + tid];
    hbar[b * HID + tid] = acc;
}

// ---------------- concat helpers ----------------
__global__ void sf_build(const float* __restrict__ hs, const float* __restrict__ s,
                         float* __restrict__ sf) {
    int idx = blockIdx.x * blockDim.x + threadIdx.x;
    if (idx >= BATCH * EDIM) return;
    int b = idx / EDIM, j = idx % EDIM;
    sf[idx] = (j < HID) ? hs[((size_t)b * TSEQ + (TSEQ - 1)) * HID + j] : s[b * FDIM + (j - HID)];
}
__global__ void ms_build(const float* __restrict__ ao, const float* __restrict__ s,
                         float* __restrict__ ms) {
    int idx = blockIdx.x * blockDim.x + threadIdx.x;
    if (idx >= BATCH * DM) return;
    int b = idx / DM, j = idx % DM;
    ms[idx] = (j < EDIM) ? ao[b * EDIM + j] : s[b * FDIM + (j - EDIM)];
}
__global__ void merged_build(const float* __restrict__ ms, const float* __restrict__ qf,
                             float* __restrict__ mg) {
    int idx = blockIdx.x * blockDim.x + threadIdx.x;
    if (idx >= BATCH * NMERG) return;
    int b = idx / NMERG, j = idx % NMERG;
    mg[idx] = (j < DM) ? ms[b * DM + j] : qf[b * 10 + (j - DM)];
}

// ---------------- 10-qubit VQC, one block per batch element --------------------------
struct c2f { float x, y; };
__device__ __forceinline__ c2f cmul(c2f a, c2f b) { return { a.x * b.x - a.y * b.y, a.x * b.y + a.y * b.x }; }
__device__ __forceinline__ c2f cadd(c2f a, c2f b) { return { a.x + b.x, a.y + b.y }; }
__device__ __forceinline__ void matmul2(c2f C[2][2], const c2f A[2][2], const c2f B[2][2]) {
    #pragma unroll
    for (int i = 0; i < 2; i++)
        #pragma unroll
        for (int j = 0; j < 2; j++)
            C[i][j] = cadd(cmul(A[i][0], B[0][j]), cmul(A[i][1], B[1][j]));
}

__global__ void vqc_kernel(const float* __restrict__ ms, const float* __restrict__ qw,
                           float* __restrict__ qfeat) {
    int b = blockIdx.x;
    __shared__ c2f psi[1024];
    __shared__ float red[512];
    __shared__ float sang[40];
    int tid = threadIdx.x;
    const float PI_F = 3.14159265358979323846f;
    psi[tid] = { 0.03125f, 0.f };
    psi[tid + 512] = { 0.03125f, 0.f };
    if (tid < 40) sang[tid] = tanhf(ms[b * DM + tid]) * PI_F;
    __syncthreads();

    for (int layer = 0; layer < 4; layer++) {
        for (int q = 0; q < 10; q++) {
            int idx = layer * 10 + q;
            float a = sang[idx];
            float w0 = qw[idx * 3 + 0], w1 = qw[idx * 3 + 1], w2 = qw[idx * 3 + 2];
            float ch, sh; sincosf(0.5f * a, &sh, &ch);
            c2f Rx[2][2] = { { {ch, 0.f}, {0.f, -sh} }, { {0.f, -sh}, {ch, 0.f} } };
            c2f Rya[2][2] = { { {ch, 0.f}, {-sh, 0.f} }, { {sh, 0.f}, {ch, 0.f} } };
            c2f T1[2][2]; matmul2(T1, Rya, Rx);
            float c0, s0; sincosf(0.5f * w0, &s0, &c0);
            c2f Rz0[2][2] = { { {c0, -s0}, {0.f, 0.f} }, { {0.f, 0.f}, {c0, s0} } };
            c2f T2[2][2]; matmul2(T2, Rz0, T1);
            float c1, s1; sincosf(0.5f * w1, &s1, &c1);
            c2f Ry1[2][2] = { { {c1, 0.f}, {-s1, 0.f} }, { {s1, 0.f}, {c1, 0.f} } };
            c2f T3[2][2]; matmul2(T3, Ry1, T2);
            float c2r, s2r; sincosf(0.5f * w2, &s2r, &c2r);
            c2f Rz2[2][2] = { { {c2r, -s2r}, {0.f, 0.f} }, { {0.f, 0.f}, {c2r, s2r} } };
            c2f U[2][2]; matmul2(U, Rz2, T3);

            int bq = 9 - q;
            int low = tid & ((1 << bq) - 1);
            int i0 = ((tid >> bq) << (bq + 1)) | low;
            int i1 = i0 | (1 << bq);
            __syncthreads();
            c2f a0 = psi[i0], a1 = psi[i1];
            psi[i0] = cadd(cmul(U[0][0], a0), cmul(U[0][1], a1));
            psi[i1] = cadd(cmul(U[1][0], a0), cmul(U[1][1], a1));
        }
        for (int qq = 0; qq < 10; qq++) {
            int ctrl = (qq < 9) ? qq : 9;
            int tgt  = (qq < 9) ? qq + 1 : 0;
            int bc = 9 - ctrl, bt = 9 - tgt;
            __syncthreads();
            if (tid < 256) {
                int lo = min(bc, bt), hi = max(bc, bt);
                int i = tid;
                i = ((i >> lo) << (lo + 1)) | (i & ((1 << lo) - 1));
                i = ((i >> hi) << (hi + 1)) | (i & ((1 << hi) - 1));
                i |= (1 << bc);
                int j0 = i;
                int j1 = i | (1 << bt);
                c2f tmp = psi[j0]; psi[j0] = psi[j1]; psi[j1] = tmp;
            }
        }
    }
    __syncthreads();
    c2f p0 = psi[tid], p1 = psi[tid + 512];
    float n0 = p0.x * p0.x + p0.y * p0.y;
    float n1 = p1.x * p1.x + p1.y * p1.y;
    for (int k = 0; k < 10; k++) {
        int bp = 9 - k;
        float s0v = ((tid >> bp) & 1) ? -n0 : n0;
        float s1v = (((tid + 512) >> bp) & 1) ? -n1 : n1;
        red[tid] = s0v + s1v;
        __syncthreads();
        for (int s = 256; s > 0; s >>= 1) { if (tid < s) red[tid] += red[tid + s]; __syncthreads(); }
        if (tid == 0) qfeat[b * 10 + k] = red[0];
        __syncthreads();
    }
}

// ---------------- host launch ----------------
#define GETSYM(p, sym) do { void* _t = nullptr; cudaGetSymbolAddress(&_t, sym); (p) = (float*)_t; } while (0)

extern "C" void kernel_launch(void* const* d_in, const int* in_sizes, int n_in,
                              void* d_out, int out_size) {
    const float* s          = (const float*)d_in[0];
    const float* lstm_s     = (const float*)d_in[1];
    const float* W_ih       = (const float*)d_in[2];
    const float* W_hh       = (const float*)d_in[3];
    const float* b_ih       = (const float*)d_in[4];
    const float* b_hh       = (const float*)d_in[5];
    const float* proj_W     = (const float*)d_in[6];
    const float* proj_b     = (const float*)d_in[7];
    const float* in_proj_W  = (const float*)d_in[8];
    const float* in_proj_b  = (const float*)d_in[9];
    const float* out_proj_W = (const float*)d_in[10];
    const float* out_proj_b = (const float*)d_in[11];
    const float* qweights   = (const float*)d_in[12];
    const float* W1         = (const float*)d_in[13];
    const float* b1         = (const float*)d_in[14];
    const float* W2         = (const float*)d_in[15];
    const float* b2         = (const float*)d_in[16];
    float* out = (float*)d_out;

    float *hs, *Wip, *Wp, *bp, *sf, *qv, *qk, *Mkp, *MA1, *Amat;
    float *vconst, *aconst, *hbar, *ao, *msb, *qfeat, *merged, *x1;
    __half *xw, *hbuf;
    int* bar;
    { void* _t = nullptr; cudaGetSymbolAddress(&_t, d_xw); xw = (__half*)_t; }
    { void* _t = nullptr; cudaGetSymbolAddress(&_t, d_hbuf); hbuf = (__half*)_t; }
    GETSYM(hs, d_hs);
    GETSYM(Wip, d_Wip); GETSYM(Wp, d_Wp);   GETSYM(bp, d_bp);   GETSYM(sf, d_sf);
    GETSYM(qv, d_q);    GETSYM(qk, d_qk);   GETSYM(Mkp, d_Mkp); GETSYM(MA1, d_MA1);
    GETSYM(Amat, d_Amat); GETSYM(vconst, d_vconst); GETSYM(aconst, d_aconst);
    GETSYM(hbar, d_hbar); GETSYM(ao, d_ao); GETSYM(msb, d_ms);  GETSYM(qfeat, d_qfeat);
    GETSYM(merged, d_merged); GETSYM(x1, d_x1);
    { void* _t = nullptr; cudaGetSymbolAddress(&_t, d_bar); bar = (int*)_t; }

    const float* Wq = in_proj_W;
    const float* Wk = in_proj_W + EDIM * EDIM;
    const float* Wv = in_proj_W + 2 * EDIM * EDIM;
    const float* bq = in_proj_b;
    const float* bv = in_proj_b + 2 * EDIM;

    cudaMemsetAsync(bar, 0, 8 * TSEQ * sizeof(int));

    // weight permutation (gate-interleaved)
    permute_kernel<<<G4, 128>>>(W_ih, W_hh, b_ih, b_hh, Wip, Wp, bp);

    // big input GEMM (fp16 tensor cores): xw[t,b,:] = X @ Wip^T + bp (fp16 out)
    xw_gemm_f16<<<dim3(G4 / 128, (BATCH * TSEQ) / 128), 256>>>(lstm_s, Wip, bp, xw);

    // persistent LSTM recurrence (all 256 steps, one kernel, fp16 tensor cores)
    lstm_persist<<<NBLK, 256>>>(xw, Wp, hs, hbuf, bar);

    // state_full = [h_last, s]; q = sf @ Wq^T + bq
    sf_build<<<(BATCH * EDIM + 255) / 256, 256>>>(hs, s, sf);
    gemm_med<false, false><<<dim3(5, 8), 256>>>(sf, Wq, bq, qv, BATCH, EDIM, EDIM, EDIM, EDIM, EDIM);

    // precompose attention matrices
    gemm_med<true, false><<<dim3(4, 5), 256>>>(Wk, proj_W, nullptr, Mkp, EDIM, HID, EDIM, EDIM, HID, HID);
    gemm_med<true, false><<<dim3(4, 8), 256>>>(qv, Mkp, nullptr, qk, BATCH, HID, EDIM, EDIM, HID, HID);
    gemm_med<true, false><<<dim3(4, 5), 256>>>(Wv, proj_W, nullptr, MA1, EDIM, HID, EDIM, EDIM, HID, HID);
    gemm_med<true, false><<<dim3(4, 5), 256>>>(out_proj_W, MA1, nullptr, Amat, EDIM, HID, EDIM, EDIM, HID, HID);
    matvec<<<1, EDIM>>>(Wv, proj_b, bv, vconst, EDIM, EDIM, EDIM);
    matvec<<<1, EDIM>>>(out_proj_W, vconst, out_proj_b, aconst, EDIM, EDIM, EDIM);

    // fused attention over hs
    attn_kernel<<<BATCH, 256>>>(hs, qk, hbar);

    // attn_out = hbar @ Amat^T + aconst; merged_state = [attn_out, s]
    gemm_med<false, false><<<dim3(5, 8), 256>>>(hbar, Amat, aconst, ao, BATCH, EDIM, HID, HID, HID, EDIM);
    ms_build<<<(BATCH * DM + 255) / 256, 256>>>(ao, s, msb);

    // VQC
    vqc_kernel<<<BATCH, 512>>>(msb, qweights, qfeat);

    // MLP
    merged_build<<<(BATCH * NMERG + 255) / 256, 256>>>(msb, qfeat, merged);
    gemm_med<false, true><<<dim3(8, 8), 256>>>(merged, W1, b1, x1, BATCH, NL1, NMERG, NMERG, NMERG, NL1);
    gemm_med<false, false><<<dim3(1, 8), 256>>>(x1, W2, b2, out, BATCH, NACT, NL1, NL1, NL1, NACT);
}